// round 1
// baseline (speedup 1.0000x reference)
#include <cuda_runtime.h>

// Problem constants
#define NB 16
#define NC 64
#define NH 256
#define NW 256
#define NK 4
#define NO 64
#define HID 17
#define TEMP 34.0f
#define SLOPE 0.2f

// Scratch (allocation-free rule: __device__ globals)
__device__ float g_pooled[NB * NC];
__device__ float g_att[NB * NK];
__device__ float g_aggw[NB * NC * 9 * NO];  // layout [b][i][k][o]
__device__ float g_aggb[NB * NO];

typedef unsigned long long ull;

__device__ __forceinline__ ull pack2(float lo, float hi) {
    ull r;
    asm("mov.b64 %0, {%1, %2};" : "=l"(r)
        : "r"(__float_as_uint(lo)), "r"(__float_as_uint(hi)));
    return r;
}
__device__ __forceinline__ ull fma2(ull a, ull b, ull c) {
    ull d;
    asm("fma.rn.f32x2 %0, %1, %2, %3;" : "=l"(d) : "l"(a), "l"(b), "l"(c));
    return d;
}
__device__ __forceinline__ float2 unpack2(ull a) {
    unsigned lo, hi;
    asm("mov.b64 {%0, %1}, %2;" : "=r"(lo), "=r"(hi) : "l"(a));
    return make_float2(__uint_as_float(lo), __uint_as_float(hi));
}

// ---------------------------------------------------------------------------
// Kernel 1: global average pool. One block per (b,c), 256 threads.
// ---------------------------------------------------------------------------
__global__ void pool_kernel(const float* __restrict__ x) {
    int bc = blockIdx.x;  // 0..1023
    const float4* p = reinterpret_cast<const float4*>(x) + (size_t)bc * (NH * NW / 4);
    float s = 0.f;
    for (int i = threadIdx.x; i < NH * NW / 4; i += 256) {
        float4 v = p[i];
        s += (v.x + v.y) + (v.z + v.w);
    }
#pragma unroll
    for (int off = 16; off; off >>= 1) s += __shfl_down_sync(0xFFFFFFFFu, s, off);
    __shared__ float ws[8];
    if ((threadIdx.x & 31) == 0) ws[threadIdx.x >> 5] = s;
    __syncthreads();
    if (threadIdx.x == 0) {
        float tot = 0.f;
#pragma unroll
        for (int w = 0; w < 8; w++) tot += ws[w];
        g_pooled[bc] = tot * (1.0f / (NH * NW));
    }
}

// ---------------------------------------------------------------------------
// Kernel 2: attention MLP + softmax(logits / T). One block of 288 threads.
// ---------------------------------------------------------------------------
__global__ void att_kernel(const float* __restrict__ fc1,   // [17,64]
                           const float* __restrict__ fc2,   // [4,17]
                           const float* __restrict__ fc2b)  // [4]
{
    __shared__ float sp[NB * NC];
    __shared__ float sf1[HID * NC];
    __shared__ float sh[NB][HID];
    int t = threadIdx.x;
    for (int i = t; i < NB * NC; i += blockDim.x) sp[i] = g_pooled[i];
    for (int i = t; i < HID * NC; i += blockDim.x) sf1[i] = fc1[i];
    __syncthreads();
    if (t < NB * HID) {
        int b = t / HID, j = t % HID;
        float s = 0.f;
#pragma unroll
        for (int c = 0; c < NC; c++) s += sp[b * NC + c] * sf1[j * NC + c];
        sh[b][j] = s >= 0.f ? s : SLOPE * s;
    }
    __syncthreads();
    if (t < NB) {
        int b = t;
        float lg[NK];
        float m = -1e30f;
#pragma unroll
        for (int k = 0; k < NK; k++) {
            float s = fc2b[k];
#pragma unroll
            for (int j = 0; j < HID; j++) s += sh[b][j] * fc2[k * HID + j];
            lg[k] = s / TEMP;
            m = fmaxf(m, lg[k]);
        }
        float den = 0.f, e[NK];
#pragma unroll
        for (int k = 0; k < NK; k++) { e[k] = expf(lg[k] - m); den += e[k]; }
        float inv = 1.0f / den;
#pragma unroll
        for (int k = 0; k < NK; k++) g_att[b * NK + k] = e[k] * inv;
    }
}

// ---------------------------------------------------------------------------
// Kernel 3: aggregate + transpose weights to [b][i][k][o]; also agg bias.
// Reads of `weight` are coalesced ((i,r) fastest); scattered 4B writes are
// cheap (2.36 MB unique).
// ---------------------------------------------------------------------------
__global__ void agg_kernel(const float* __restrict__ weight,  // [K][O][I][3][3]
                           const float* __restrict__ bias_k)  // [K][O]
{
    int idx = blockIdx.x * 256 + threadIdx.x;
    const int TOT = NB * NO * NC * 9;  // 589824, idx = ((b*64+o)*64+i)*9+r
    if (idx < TOT) {
        int r = idx % 9;
        int t = idx / 9;
        int i = t % NC; t /= NC;
        int o = t % NO;
        int b = t / NO;
        float a0 = g_att[b * NK + 0];
        float a1 = g_att[b * NK + 1];
        float a2 = g_att[b * NK + 2];
        float a3 = g_att[b * NK + 3];
        int wb = (o * NC + i) * 9 + r;           // + k * (NO*NC*9)
        const int KS = NO * NC * 9;              // 36864
        float s = a0 * weight[wb] + a1 * weight[wb + KS] +
                  a2 * weight[wb + 2 * KS] + a3 * weight[wb + 3 * KS];
        g_aggw[((b * NC + i) * 9 + r) * NO + o] = s;
    }
    if (idx < NB * NO) {
        int b = idx >> 6, o = idx & 63;
        float s = 0.f;
#pragma unroll
        for (int k = 0; k < NK; k++) s += g_att[b * NK + k] * bias_k[k * NO + o];
        g_aggb[idx] = s;
    }
}

// ---------------------------------------------------------------------------
// Kernel 4: per-sample 64->64 3x3 conv, pad 1, + bias.
// Block: 256 threads = 32(x) x 8(ty); tile 32 wide x 16 tall; 16 O channels.
// Each thread: 2 vertically-adjacent pixels in f32x2 packed accumulators.
// Weights duplicated in smem so ld.shared.b64 yields {w,w}.
// ---------------------------------------------------------------------------
#define TW 32
#define TH 16
#define OT 16
#define ICC 8

__global__ void __launch_bounds__(256, 2)
conv_kernel(const float* __restrict__ x, float* __restrict__ out) {
    const int og = blockIdx.x;           // 0..3 (fastest -> og-blocks share x tile in L2)
    const int tile = blockIdx.y;         // 0..127
    const int b = blockIdx.z;            // 0..15
    const int tx = threadIdx.x & 31;
    const int ty = threadIdx.x >> 5;     // 0..7
    const int x0 = (tile & 7) * TW;
    const int y0 = (tile >> 3) * TH;

    __shared__ __align__(16) float sx[ICC][TH + 2][TW + 2];   // [8][18][34]
    __shared__ __align__(16) float sw[ICC][9][OT][2];         // duplicated pairs

    ull acc[OT];
#pragma unroll
    for (int o = 0; o < OT; o++) acc[o] = 0ull;

    for (int c0 = 0; c0 < NC; c0 += ICC) {
        __syncthreads();
        // ---- stage input tile (with halo, zero-padded) ----
        for (int i = threadIdx.x; i < ICC * (TH + 2) * (TW + 2); i += 256) {
            int ci = i / ((TH + 2) * (TW + 2));
            int rem = i - ci * ((TH + 2) * (TW + 2));
            int r = rem / (TW + 2);
            int cc = rem - r * (TW + 2);
            int gy = y0 + r - 1, gx = x0 + cc - 1;
            float v = 0.f;
            if ((unsigned)gy < (unsigned)NH && (unsigned)gx < (unsigned)NW)
                v = x[((b * NC + c0 + ci) * NH + gy) * NW + gx];
            (&sx[0][0][0])[i] = v;
        }
        // ---- stage weights (duplicated) ----
        for (int i = threadIdx.x; i < ICC * 9 * OT; i += 256) {
            int ci = i / (9 * OT);
            int rem = i - ci * 9 * OT;
            int kk = rem / OT;
            int o = rem - kk * OT;
            float w = g_aggw[((b * NC + c0 + ci) * 9 + kk) * NO + og * OT + o];
            sw[ci][kk][o][0] = w;
            sw[ci][kk][o][1] = w;
        }
        __syncthreads();

#pragma unroll 1
        for (int ci = 0; ci < ICC; ci++) {
            // 12 input values covering both pixels' 3x3 windows
            float v[4][3];
#pragma unroll
            for (int ry = 0; ry < 4; ry++)
#pragma unroll
                for (int cx = 0; cx < 3; cx++)
                    v[ry][cx] = sx[ci][ty * 2 + ry][tx + cx];
            ull xp[9];
#pragma unroll
            for (int ky = 0; ky < 3; ky++)
#pragma unroll
                for (int kx = 0; kx < 3; kx++)
                    xp[ky * 3 + kx] = pack2(v[ky][kx], v[ky + 1][kx]);

            const ull* wrow = reinterpret_cast<const ull*>(&sw[0][0][0][0]) + ci * 9 * OT;
#pragma unroll
            for (int k = 0; k < 9; k++) {
#pragma unroll
                for (int o = 0; o < OT; o++) {
                    acc[o] = fma2(xp[k], wrow[k * OT + o], acc[o]);
                }
            }
        }
    }

    // ---- epilogue: bias + store ----
    const int row = y0 + ty * 2;
    const int col = x0 + tx;
#pragma unroll
    for (int o = 0; o < OT; o++) {
        float bv = g_aggb[b * NO + og * OT + o];
        float2 a = unpack2(acc[o]);
        size_t base = (((size_t)b * NO + og * OT + o) * NH + row) * NW + col;
        out[base] = a.x + bv;
        out[base + NW] = a.y + bv;
    }
}

// ---------------------------------------------------------------------------
extern "C" void kernel_launch(void* const* d_in, const int* in_sizes, int n_in,
                              void* d_out, int out_size) {
    const float* x      = (const float*)d_in[0];
    const float* fc1_w  = (const float*)d_in[1];
    const float* fc2_w  = (const float*)d_in[2];
    const float* fc2_b  = (const float*)d_in[3];
    const float* weight = (const float*)d_in[4];
    const float* bias_k = (const float*)d_in[5];
    float* out = (float*)d_out;

    pool_kernel<<<NB * NC, 256>>>(x);
    att_kernel<<<1, 288>>>(fc1_w, fc2_w, fc2_b);
    agg_kernel<<<(NB * NO * NC * 9 + 255) / 256, 256>>>(weight, bias_k);
    conv_kernel<<<dim3(4, (NH / TH) * (NW / TW), NB), 256>>>(x, out);
}

// round 3
// speedup vs baseline: 1.0372x; 1.0372x over previous
#include <cuda_runtime.h>

// Problem constants
#define NB 16
#define NC 64
#define NH 256
#define NW 256
#define NK 4
#define NO 64
#define HID 17
#define TEMP 34.0f
#define SLOPE 0.2f

// Scratch (allocation-free rule: __device__ globals)
__device__ float g_pooled[NB * NC];
__device__ float g_att[NB * NK];
__device__ float g_aggw[NB * NC * 9 * NO];  // layout [b][i][k][o]
__device__ float g_aggb[NB * NO];

typedef unsigned long long ull;

__device__ __forceinline__ ull pack2(float lo, float hi) {
    ull r;
    asm("mov.b64 %0, {%1, %2};" : "=l"(r)
        : "r"(__float_as_uint(lo)), "r"(__float_as_uint(hi)));
    return r;
}
__device__ __forceinline__ ull fma2(ull a, ull b, ull c) {
    ull d;
    asm("fma.rn.f32x2 %0, %1, %2, %3;" : "=l"(d) : "l"(a), "l"(b), "l"(c));
    return d;
}
__device__ __forceinline__ float2 unpack2(ull a) {
    unsigned lo, hi;
    asm("mov.b64 {%0, %1}, %2;" : "=r"(lo), "=r"(hi) : "l"(a));
    return make_float2(__uint_as_float(lo), __uint_as_float(hi));
}

// ---------------------------------------------------------------------------
// Kernel 1: global average pool. One block per (b,c), 256 threads.
// ---------------------------------------------------------------------------
__global__ void pool_kernel(const float* __restrict__ x) {
    int bc = blockIdx.x;  // 0..1023
    const float4* p = reinterpret_cast<const float4*>(x) + (size_t)bc * (NH * NW / 4);
    float s = 0.f;
    for (int i = threadIdx.x; i < NH * NW / 4; i += 256) {
        float4 v = p[i];
        s += (v.x + v.y) + (v.z + v.w);
    }
#pragma unroll
    for (int off = 16; off; off >>= 1) s += __shfl_down_sync(0xFFFFFFFFu, s, off);
    __shared__ float ws[8];
    if ((threadIdx.x & 31) == 0) ws[threadIdx.x >> 5] = s;
    __syncthreads();
    if (threadIdx.x == 0) {
        float tot = 0.f;
#pragma unroll
        for (int w = 0; w < 8; w++) tot += ws[w];
        g_pooled[bc] = tot * (1.0f / (NH * NW));
    }
}

// ---------------------------------------------------------------------------
// Kernel 2: attention MLP + softmax(logits / T). One block of 288 threads.
// ---------------------------------------------------------------------------
__global__ void att_kernel(const float* __restrict__ fc1,   // [17,64]
                           const float* __restrict__ fc2,   // [4,17]
                           const float* __restrict__ fc2b)  // [4]
{
    __shared__ float sp[NB * NC];
    __shared__ float sf1[HID * NC];
    __shared__ float sh[NB][HID];
    int t = threadIdx.x;
    for (int i = t; i < NB * NC; i += blockDim.x) sp[i] = g_pooled[i];
    for (int i = t; i < HID * NC; i += blockDim.x) sf1[i] = fc1[i];
    __syncthreads();
    if (t < NB * HID) {
        int b = t / HID, j = t % HID;
        float s = 0.f;
#pragma unroll
        for (int c = 0; c < NC; c++) s += sp[b * NC + c] * sf1[j * NC + c];
        sh[b][j] = s >= 0.f ? s : SLOPE * s;
    }
    __syncthreads();
    if (t < NB) {
        int b = t;
        float lg[NK];
        float m = -1e30f;
#pragma unroll
        for (int k = 0; k < NK; k++) {
            float s = fc2b[k];
#pragma unroll
            for (int j = 0; j < HID; j++) s += sh[b][j] * fc2[k * HID + j];
            lg[k] = s / TEMP;
            m = fmaxf(m, lg[k]);
        }
        float den = 0.f, e[NK];
#pragma unroll
        for (int k = 0; k < NK; k++) { e[k] = expf(lg[k] - m); den += e[k]; }
        float inv = 1.0f / den;
#pragma unroll
        for (int k = 0; k < NK; k++) g_att[b * NK + k] = e[k] * inv;
    }
}

// ---------------------------------------------------------------------------
// Kernel 3: aggregate + transpose weights to [b][i][k][o]; also agg bias.
// ---------------------------------------------------------------------------
__global__ void agg_kernel(const float* __restrict__ weight,  // [K][O][I][3][3]
                           const float* __restrict__ bias_k)  // [K][O]
{
    int idx = blockIdx.x * 256 + threadIdx.x;
    const int TOT = NB * NO * NC * 9;  // 589824
    if (idx < TOT) {
        int r = idx % 9;
        int t = idx / 9;
        int i = t % NC; t /= NC;
        int o = t % NO;
        int b = t / NO;
        float a0 = g_att[b * NK + 0];
        float a1 = g_att[b * NK + 1];
        float a2 = g_att[b * NK + 2];
        float a3 = g_att[b * NK + 3];
        int wb = (o * NC + i) * 9 + r;
        const int KS = NO * NC * 9;
        float s = a0 * weight[wb] + a1 * weight[wb + KS] +
                  a2 * weight[wb + 2 * KS] + a3 * weight[wb + 3 * KS];
        g_aggw[((b * NC + i) * 9 + r) * NO + o] = s;
    }
    if (idx < NB * NO) {
        int b = idx >> 6, o = idx & 63;
        float s = 0.f;
#pragma unroll
        for (int k = 0; k < NK; k++) s += g_att[b * NK + k] * bias_k[k * NO + o];
        g_aggb[idx] = s;
    }
}

// ---------------------------------------------------------------------------
// Kernel 4: per-sample 64->64 3x3 conv, pad 1, + bias.
// Block: 256 threads = 32(tx) x 8(ty). Tile: 32 wide x 64 tall, 8 O channels.
// Each thread: 8 vertically-adjacent pixels (4 f32x2 pairs) x 8 o = 32 accs.
// One weight LDS.64 (block-broadcast) feeds 4 FMA2s.
// ---------------------------------------------------------------------------
#define TW 32
#define TH 64
#define OT 8
#define ICC 4
#define SXW (TW + 2)  // 34
#define SXH (TH + 2)  // 66

__global__ void __launch_bounds__(256, 2)
conv_kernel(const float* __restrict__ x, float* __restrict__ out) {
    const int og = blockIdx.x;           // 0..7 (fastest -> og-blocks share x tile in L2)
    const int tile = blockIdx.y;         // 0..31  (8 xtiles * 4 ytiles)
    const int b = blockIdx.z;            // 0..15
    const int tx = threadIdx.x & 31;
    const int ty = threadIdx.x >> 5;     // 0..7
    const int x0 = (tile & 7) * TW;
    const int y0 = (tile >> 3) * TH;

    __shared__ __align__(16) float sx[ICC][SXH][SXW];   // 4*66*34*4 = 35904 B
    __shared__ __align__(16) float sw[ICC][9][OT][2];   // duplicated pairs, 2304 B

    ull acc[4][OT];
#pragma unroll
    for (int p = 0; p < 4; p++)
#pragma unroll
        for (int o = 0; o < OT; o++) acc[p][o] = 0ull;

    const int row_lo = ty * 8;  // thread's first output row (tile-local)

    for (int c0 = 0; c0 < NC; c0 += ICC) {
        __syncthreads();
        // ---- stage input tile (with halo, zero-padded) ----
        for (int i = threadIdx.x; i < ICC * SXH * SXW; i += 256) {
            int ci = i / (SXH * SXW);
            int rem = i - ci * (SXH * SXW);
            int r = rem / SXW;
            int cc = rem - r * SXW;
            int gy = y0 + r - 1, gx = x0 + cc - 1;
            float v = 0.f;
            if ((unsigned)gy < (unsigned)NH && (unsigned)gx < (unsigned)NW)
                v = x[((b * NC + c0 + ci) * NH + gy) * NW + gx];
            (&sx[0][0][0])[i] = v;
        }
        // ---- stage weights (duplicated pairs for f32x2) ----
        // NOTE: 288 elements > 256 threads, MUST be a strided loop.
        for (int i = threadIdx.x; i < ICC * 9 * OT; i += 256) {
            int ci = i / (9 * OT);
            int rem = i - ci * 9 * OT;
            int kk = rem / OT;
            int o = rem - kk * OT;
            float w = g_aggw[((b * NC + c0 + ci) * 9 + kk) * NO + og * OT + o];
            sw[ci][kk][o][0] = w;
            sw[ci][kk][o][1] = w;
        }
        __syncthreads();

#pragma unroll 1
        for (int ci = 0; ci < ICC; ci++) {
            // 10 rows x 3 cols of input covering the 8-pixel column's windows
            float v[10][3];
#pragma unroll
            for (int j = 0; j < 10; j++)
#pragma unroll
                for (int cx = 0; cx < 3; cx++)
                    v[j][cx] = sx[ci][row_lo + j][tx + cx];

            const ull* wrow = reinterpret_cast<const ull*>(&sw[0][0][0][0]) + ci * 9 * OT;
#pragma unroll
            for (int k = 0; k < 9; k++) {
                const int ky = k / 3, kx = k % 3;
                // 4 packed input pairs for this tap (reused across all 8 o)
                ull xp[4];
#pragma unroll
                for (int p = 0; p < 4; p++)
                    xp[p] = pack2(v[2 * p + ky][kx], v[2 * p + ky + 1][kx]);
#pragma unroll
                for (int o = 0; o < OT; o++) {
                    ull wv = wrow[k * OT + o];  // LDS.64 broadcast
#pragma unroll
                    for (int p = 0; p < 4; p++)
                        acc[p][o] = fma2(xp[p], wv, acc[p][o]);
                }
            }
        }
    }

    // ---- epilogue: bias + store (coalesced: lanes = 32 consecutive cols) ----
    const int col = x0 + tx;
#pragma unroll
    for (int o = 0; o < OT; o++) {
        float bv = g_aggb[b * NO + og * OT + o];
        size_t base = (((size_t)b * NO + og * OT + o) * NH + (y0 + row_lo)) * NW + col;
#pragma unroll
        for (int p = 0; p < 4; p++) {
            float2 a = unpack2(acc[p][o]);
            out[base + (size_t)(2 * p) * NW] = a.x + bv;
            out[base + (size_t)(2 * p + 1) * NW] = a.y + bv;
        }
    }
}

// ---------------------------------------------------------------------------
extern "C" void kernel_launch(void* const* d_in, const int* in_sizes, int n_in,
                              void* d_out, int out_size) {
    const float* x      = (const float*)d_in[0];
    const float* fc1_w  = (const float*)d_in[1];
    const float* fc2_w  = (const float*)d_in[2];
    const float* fc2_b  = (const float*)d_in[3];
    const float* weight = (const float*)d_in[4];
    const float* bias_k = (const float*)d_in[5];
    float* out = (float*)d_out;

    pool_kernel<<<NB * NC, 256>>>(x);
    att_kernel<<<1, 288>>>(fc1_w, fc2_w, fc2_b);
    agg_kernel<<<(NB * NO * NC * 9 + 255) / 256, 256>>>(weight, bias_k);
    conv_kernel<<<dim3(NO / OT, (NW / TW) * (NH / TH), NB), 256>>>(x, out);
}

// round 4
// speedup vs baseline: 1.1626x; 1.1209x over previous
#include <cuda_runtime.h>

// Problem constants
#define NB 16
#define NC 64
#define NH 256
#define NW 256
#define NK 4
#define NO 64
#define HID 17
#define TEMP 34.0f
#define SLOPE 0.2f

// Scratch (allocation-free rule: __device__ globals)
__device__ float g_pooled[NB * NC];
__device__ float g_att[NB * NK];
__device__ float g_aggw[NB * NC * 9 * NO];  // layout [b][i][k][o]
__device__ float g_aggb[NB * NO];

typedef unsigned long long ull;

__device__ __forceinline__ ull pack2(float lo, float hi) {
    ull r;
    asm("mov.b64 %0, {%1, %2};" : "=l"(r)
        : "r"(__float_as_uint(lo)), "r"(__float_as_uint(hi)));
    return r;
}
__device__ __forceinline__ ull fma2(ull a, ull b, ull c) {
    ull d;
    asm("fma.rn.f32x2 %0, %1, %2, %3;" : "=l"(d) : "l"(a), "l"(b), "l"(c));
    return d;
}
__device__ __forceinline__ float2 unpack2(ull a) {
    unsigned lo, hi;
    asm("mov.b64 {%0, %1}, %2;" : "=r"(lo), "=r"(hi) : "l"(a));
    return make_float2(__uint_as_float(lo), __uint_as_float(hi));
}

// ---------------------------------------------------------------------------
// Kernel 1: global average pool. One block per (b,c), 256 threads.
// ---------------------------------------------------------------------------
__global__ void pool_kernel(const float* __restrict__ x) {
    int bc = blockIdx.x;
    const float4* p = reinterpret_cast<const float4*>(x) + (size_t)bc * (NH * NW / 4);
    float s = 0.f;
    for (int i = threadIdx.x; i < NH * NW / 4; i += 256) {
        float4 v = p[i];
        s += (v.x + v.y) + (v.z + v.w);
    }
#pragma unroll
    for (int off = 16; off; off >>= 1) s += __shfl_down_sync(0xFFFFFFFFu, s, off);
    __shared__ float ws[8];
    if ((threadIdx.x & 31) == 0) ws[threadIdx.x >> 5] = s;
    __syncthreads();
    if (threadIdx.x == 0) {
        float tot = 0.f;
#pragma unroll
        for (int w = 0; w < 8; w++) tot += ws[w];
        g_pooled[bc] = tot * (1.0f / (NH * NW));
    }
}

// ---------------------------------------------------------------------------
// Kernel 2: attention MLP + softmax(logits / T). One block of 288 threads.
// ---------------------------------------------------------------------------
__global__ void att_kernel(const float* __restrict__ fc1,
                           const float* __restrict__ fc2,
                           const float* __restrict__ fc2b) {
    __shared__ float sp[NB * NC];
    __shared__ float sf1[HID * NC];
    __shared__ float sh[NB][HID];
    int t = threadIdx.x;
    for (int i = t; i < NB * NC; i += blockDim.x) sp[i] = g_pooled[i];
    for (int i = t; i < HID * NC; i += blockDim.x) sf1[i] = fc1[i];
    __syncthreads();
    if (t < NB * HID) {
        int b = t / HID, j = t % HID;
        float s = 0.f;
#pragma unroll
        for (int c = 0; c < NC; c++) s += sp[b * NC + c] * sf1[j * NC + c];
        sh[b][j] = s >= 0.f ? s : SLOPE * s;
    }
    __syncthreads();
    if (t < NB) {
        int b = t;
        float lg[NK];
        float m = -1e30f;
#pragma unroll
        for (int k = 0; k < NK; k++) {
            float s = fc2b[k];
#pragma unroll
            for (int j = 0; j < HID; j++) s += sh[b][j] * fc2[k * HID + j];
            lg[k] = s / TEMP;
            m = fmaxf(m, lg[k]);
        }
        float den = 0.f, e[NK];
#pragma unroll
        for (int k = 0; k < NK; k++) { e[k] = expf(lg[k] - m); den += e[k]; }
        float inv = 1.0f / den;
#pragma unroll
        for (int k = 0; k < NK; k++) g_att[b * NK + k] = e[k] * inv;
    }
}

// ---------------------------------------------------------------------------
// Kernel 3: aggregate + transpose weights to [b][i][k][o]; also agg bias.
// ---------------------------------------------------------------------------
__global__ void agg_kernel(const float* __restrict__ weight,
                           const float* __restrict__ bias_k) {
    int idx = blockIdx.x * 256 + threadIdx.x;
    const int TOT = NB * NO * NC * 9;
    if (idx < TOT) {
        int r = idx % 9;
        int t = idx / 9;
        int i = t % NC; t /= NC;
        int o = t % NO;
        int b = t / NO;
        float a0 = g_att[b * NK + 0];
        float a1 = g_att[b * NK + 1];
        float a2 = g_att[b * NK + 2];
        float a3 = g_att[b * NK + 3];
        int wb = (o * NC + i) * 9 + r;
        const int KS = NO * NC * 9;
        float s = a0 * weight[wb] + a1 * weight[wb + KS] +
                  a2 * weight[wb + 2 * KS] + a3 * weight[wb + 3 * KS];
        g_aggw[((b * NC + i) * 9 + r) * NO + o] = s;
    }
    if (idx < NB * NO) {
        int b = idx >> 6, o = idx & 63;
        float s = 0.f;
#pragma unroll
        for (int k = 0; k < NK; k++) s += g_att[b * NK + k] * bias_k[k * NO + o];
        g_aggb[idx] = s;
    }
}

// ---------------------------------------------------------------------------
// Kernel 4: conv. 1 CTA/SM, double-buffered cp.async staging, wv-prefetch.
// Block 256 = 32(tx) x 8(ty); tile 32w x 64h; 8 o-channels; 8 px/thread.
// ---------------------------------------------------------------------------
#define TW 32
#define TH 64
#define OT 8
#define ICC 4
#define SXW (TW + 2)                 // 34
#define SXH (TH + 2)                 // 66
#define SXN (ICC * SXH * SXW)        // 8976 floats per buffer
#define SWN (ICC * 9 * OT)           // 288 weights per chunk
#define CHUNKS (NC / ICC)            // 16
#define CONV_SMEM ((2 * SXN + 2 * 2 * SWN) * 4)  // 76416 B

__device__ __forceinline__ void cp_async4(unsigned dst, const float* src, int srcsz) {
    asm volatile("cp.async.ca.shared.global [%0], [%1], 4, %2;"
                 :: "r"(dst), "l"(src), "r"(srcsz));
}
__device__ __forceinline__ void cp_commit() {
    asm volatile("cp.async.commit_group;");
}

__global__ void __launch_bounds__(256, 1)
conv_kernel(const float* __restrict__ x, float* __restrict__ out) {
    extern __shared__ float smem[];
    float* SX = smem;                 // [2][SXN]
    float* SW = smem + 2 * SXN;       // [2][2*SWN] duplicated pairs

    const int og = blockIdx.x;        // 0..7
    const int tile = blockIdx.y;      // 0..31
    const int b = blockIdx.z;         // 0..15
    const int tx = threadIdx.x & 31;
    const int ty = threadIdx.x >> 5;
    const int x0 = (tile & 7) * TW;
    const int y0 = (tile >> 3) * TH;
    const int row_lo = ty * 8;

    const unsigned sx_u32 = (unsigned)__cvta_generic_to_shared(SX);

    // Per-thread weight-gather constants: element idx and idx+256
    const int t = threadIdx.x;
    int ci_a = t / (9 * OT), rm_a = t % (9 * OT);
    int kk_a = rm_a / OT, o_a = rm_a % OT;
    const float* wg_a = g_aggw + ((size_t)(b * NC + ci_a) * 9 + kk_a) * NO + og * OT + o_a;
    int t2 = t + 256;
    int ci_b = t2 / (9 * OT), rm_b = t2 % (9 * OT);
    int kk_b = rm_b / OT, o_b = rm_b % OT;
    const float* wg_b = g_aggw + ((size_t)(b * NC + ci_b) * 9 + kk_b) * NO + og * OT + o_b;
    const size_t wstep = (size_t)ICC * 9 * NO;  // per-chunk advance

    ull acc[4][OT];
#pragma unroll
    for (int p = 0; p < 4; p++)
#pragma unroll
        for (int o = 0; o < OT; o++) acc[p][o] = 0ull;

    // ---- stage_x(chunk, buf) as a macro-style inline ----
#define STAGE_X(CHUNK, BUF)                                                     \
    {                                                                           \
        const float* xb = x + ((size_t)b * NC + (CHUNK) * ICC) * (NH * NW);     \
        for (int i = threadIdx.x; i < SXN; i += 256) {                          \
            int ci = i / (SXH * SXW);                                           \
            int rem = i - ci * (SXH * SXW);                                     \
            int r = rem / SXW;                                                  \
            int cc = rem - r * SXW;                                             \
            int gy = y0 + r - 1, gx = x0 + cc - 1;                              \
            bool ok = ((unsigned)gy < (unsigned)NH) && ((unsigned)gx < (unsigned)NW); \
            const float* src = xb + (size_t)ci * (NH * NW) + (ok ? gy * NW + gx : 0); \
            cp_async4(sx_u32 + ((BUF) * SXN + i) * 4, src, ok ? 4 : 0);         \
        }                                                                       \
        cp_commit();                                                            \
    }

    // prologue
    STAGE_X(0, 0);
    float w0 = *wg_a;
    float w1 = (t < 32) ? *wg_b : 0.f;

#pragma unroll 1
    for (int c = 0; c < CHUNKS; c++) {
        const int cur = c & 1;
        if (c + 1 < CHUNKS) {
            STAGE_X(c + 1, cur ^ 1);
            asm volatile("cp.async.wait_group 1;");
        } else {
            asm volatile("cp.async.wait_group 0;");
        }
        // store this chunk's weights (duplicated pairs)
        *reinterpret_cast<ull*>(&SW[cur * 2 * SWN + t * 2]) = pack2(w0, w0);
        if (t < 32)
            *reinterpret_cast<ull*>(&SW[cur * 2 * SWN + (t + 256) * 2]) = pack2(w1, w1);
        __syncthreads();
        // prefetch next chunk's weights (latency hidden by compute)
        if (c + 1 < CHUNKS) {
            w0 = wg_a[(size_t)(c + 1) * wstep];
            if (t < 32) w1 = wg_b[(size_t)(c + 1) * wstep];
        }

        // ---- compute from buffer `cur` ----
#pragma unroll 1
        for (int ci = 0; ci < ICC; ci++) {
            float v[10][3];
#pragma unroll
            for (int j = 0; j < 10; j++)
#pragma unroll
                for (int cx = 0; cx < 3; cx++)
                    v[j][cx] = SX[cur * SXN + ci * (SXH * SXW) + (row_lo + j) * SXW + tx + cx];

            const ull* wbase = reinterpret_cast<const ull*>(&SW[cur * 2 * SWN]) + ci * 9 * OT;
            ull wv[OT];
#pragma unroll
            for (int o = 0; o < OT; o++) wv[o] = wbase[o];

#pragma unroll
            for (int k = 0; k < 9; k++) {
                ull wn[OT];
#pragma unroll
                for (int o = 0; o < OT; o++)
                    wn[o] = (k < 8) ? wbase[(k + 1) * OT + o] : wv[o];
                const int ky = k / 3, kx = k % 3;
                ull xp[4];
#pragma unroll
                for (int p = 0; p < 4; p++)
                    xp[p] = pack2(v[2 * p + ky][kx], v[2 * p + ky + 1][kx]);
#pragma unroll
                for (int o = 0; o < OT; o++)
#pragma unroll
                    for (int p = 0; p < 4; p++)
                        acc[p][o] = fma2(xp[p], wv[o], acc[p][o]);
#pragma unroll
                for (int o = 0; o < OT; o++) wv[o] = wn[o];
            }
        }
        __syncthreads();
    }

    // ---- epilogue: bias + store ----
    const int col = x0 + tx;
#pragma unroll
    for (int o = 0; o < OT; o++) {
        float bv = g_aggb[b * NO + og * OT + o];
        size_t base = (((size_t)b * NO + og * OT + o) * NH + (y0 + row_lo)) * NW + col;
#pragma unroll
        for (int p = 0; p < 4; p++) {
            float2 a = unpack2(acc[p][o]);
            out[base + (size_t)(2 * p) * NW] = a.x + bv;
            out[base + (size_t)(2 * p + 1) * NW] = a.y + bv;
        }
    }
#undef STAGE_X
}

// ---------------------------------------------------------------------------
extern "C" void kernel_launch(void* const* d_in, const int* in_sizes, int n_in,
                              void* d_out, int out_size) {
    const float* x      = (const float*)d_in[0];
    const float* fc1_w  = (const float*)d_in[1];
    const float* fc2_w  = (const float*)d_in[2];
    const float* fc2_b  = (const float*)d_in[3];
    const float* weight = (const float*)d_in[4];
    const float* bias_k = (const float*)d_in[5];
    float* out = (float*)d_out;

    cudaFuncSetAttribute(conv_kernel, cudaFuncAttributeMaxDynamicSharedMemorySize,
                         CONV_SMEM);

    pool_kernel<<<NB * NC, 256>>>(x);
    att_kernel<<<1, 288>>>(fc1_w, fc2_w, fc2_b);
    agg_kernel<<<(NB * NO * NC * 9 + 255) / 256, 256>>>(weight, bias_k);
    conv_kernel<<<dim3(NO / OT, (NW / TW) * (NH / TH), NB), 256, CONV_SMEM>>>(x, out);
}

// round 6
// speedup vs baseline: 1.1926x; 1.0258x over previous
#include <cuda_runtime.h>
#include <cuda_bf16.h>
#include <cstdint>

#define NB 16
#define NC 64
#define NH 256
#define NW 256
#define NK 4
#define NO 64
#define HID 17
#define TEMP 34.0f
#define SLOPE 0.2f

// Scratch
__device__ float g_pooled[NB * NC];
__device__ float g_att[NB * NK];
__device__ unsigned g_aggws[NB * 9 * NC * NO];  // (bf16hi | bf16lo<<16), [b][tap][c][o]
__device__ float g_aggb[NB * NO];

__device__ __forceinline__ unsigned smem_u32(const void* p) {
    unsigned a;
    asm("{ .reg .u64 t; cvta.to.shared.u64 t, %1; cvt.u32.u64 %0, t; }" : "=r"(a) : "l"(p));
    return a;
}

__device__ __forceinline__ void ldmatrix_x4(unsigned& r0, unsigned& r1, unsigned& r2,
                                            unsigned& r3, unsigned addr) {
    asm volatile("ldmatrix.sync.aligned.m8n8.x4.shared.b16 {%0,%1,%2,%3}, [%4];"
                 : "=r"(r0), "=r"(r1), "=r"(r2), "=r"(r3) : "r"(addr));
}

__device__ __forceinline__ void mma16816(float* d, unsigned a0, unsigned a1, unsigned a2,
                                         unsigned a3, unsigned b0, unsigned b1) {
    asm volatile(
        "mma.sync.aligned.m16n8k16.row.col.f32.bf16.bf16.f32 "
        "{%0,%1,%2,%3}, {%4,%5,%6,%7}, {%8,%9}, {%0,%1,%2,%3};"
        : "+f"(d[0]), "+f"(d[1]), "+f"(d[2]), "+f"(d[3])
        : "r"(a0), "r"(a1), "r"(a2), "r"(a3), "r"(b0), "r"(b1));
}

// ---------------------------------------------------------------------------
// Kernel 1: global average pool
// ---------------------------------------------------------------------------
__global__ void pool_kernel(const float* __restrict__ x) {
    int bc = blockIdx.x;
    const float4* p = reinterpret_cast<const float4*>(x) + (size_t)bc * (NH * NW / 4);
    float s = 0.f;
    for (int i = threadIdx.x; i < NH * NW / 4; i += 256) {
        float4 v = p[i];
        s += (v.x + v.y) + (v.z + v.w);
    }
#pragma unroll
    for (int off = 16; off; off >>= 1) s += __shfl_down_sync(0xFFFFFFFFu, s, off);
    __shared__ float ws[8];
    if ((threadIdx.x & 31) == 0) ws[threadIdx.x >> 5] = s;
    __syncthreads();
    if (threadIdx.x == 0) {
        float tot = 0.f;
#pragma unroll
        for (int w = 0; w < 8; w++) tot += ws[w];
        g_pooled[bc] = tot * (1.0f / (NH * NW));
    }
}

// ---------------------------------------------------------------------------
// Kernel 2: attention MLP + softmax
// ---------------------------------------------------------------------------
__global__ void att_kernel(const float* __restrict__ fc1,
                           const float* __restrict__ fc2,
                           const float* __restrict__ fc2b) {
    __shared__ float sp[NB * NC];
    __shared__ float sf1[HID * NC];
    __shared__ float sh[NB][HID];
    int t = threadIdx.x;
    for (int i = t; i < NB * NC; i += blockDim.x) sp[i] = g_pooled[i];
    for (int i = t; i < HID * NC; i += blockDim.x) sf1[i] = fc1[i];
    __syncthreads();
    if (t < NB * HID) {
        int b = t / HID, j = t % HID;
        float s = 0.f;
#pragma unroll
        for (int c = 0; c < NC; c++) s += sp[b * NC + c] * sf1[j * NC + c];
        sh[b][j] = s >= 0.f ? s : SLOPE * s;
    }
    __syncthreads();
    if (t < NB) {
        int b = t;
        float lg[NK];
        float m = -1e30f;
#pragma unroll
        for (int k = 0; k < NK; k++) {
            float s = fc2b[k];
#pragma unroll
            for (int j = 0; j < HID; j++) s += sh[b][j] * fc2[k * HID + j];
            lg[k] = s / TEMP;
            m = fmaxf(m, lg[k]);
        }
        float den = 0.f, e[NK];
#pragma unroll
        for (int k = 0; k < NK; k++) { e[k] = expf(lg[k] - m); den += e[k]; }
        float inv = 1.0f / den;
#pragma unroll
        for (int k = 0; k < NK; k++) g_att[b * NK + k] = e[k] * inv;
    }
}

// ---------------------------------------------------------------------------
// Kernel 3: aggregate weights -> split bf16 packed, layout [b][tap][c][o]
// ---------------------------------------------------------------------------
__global__ void agg_kernel(const float* __restrict__ weight,  // [K][O][I][3][3]
                           const float* __restrict__ bias_k) {
    int idx = blockIdx.x * 256 + threadIdx.x;
    const int TOT = NB * 9 * NC * NO;  // 589824
    if (idx < TOT) {
        int o = idx & 63;
        int t1 = idx >> 6;
        int c = t1 & 63;
        int t2 = t1 >> 6;
        int tap = t2 % 9;
        int b = t2 / 9;
        const int KS = NO * NC * 9;
        int wb = (o * NC + c) * 9 + tap;
        float s = g_att[b * NK + 0] * weight[wb] +
                  g_att[b * NK + 1] * weight[wb + KS] +
                  g_att[b * NK + 2] * weight[wb + 2 * KS] +
                  g_att[b * NK + 3] * weight[wb + 3 * KS];
        __nv_bfloat16 hi = __float2bfloat16(s);
        float r = s - __bfloat162float(hi);
        __nv_bfloat16 lo = __float2bfloat16(r);
        g_aggws[idx] = (unsigned)__bfloat16_as_ushort(hi) |
                       ((unsigned)__bfloat16_as_ushort(lo) << 16);
    }
    if (idx < NB * NO) {
        int b = idx >> 6, o = idx & 63;
        float s = 0.f;
#pragma unroll
        for (int k = 0; k < NK; k++) s += g_att[b * NK + k] * bias_k[k * NO + o];
        g_aggb[idx] = s;
    }
}

// ---------------------------------------------------------------------------
// Kernel 4: mma.sync bf16 implicit-GEMM conv.
// CTA = (b, y, half): M=128 px x N=64 out, K = 9 taps x 64 ch x 3 split terms.
// X planes [3*130 rows][64 ch] bf16, row stride 72 (144 B, conflict-free).
// ---------------------------------------------------------------------------
#define XSTR 72                       // bf16 per row (stride)
#define XROWS (3 * 130)               // 390
#define OFF_XH 0
#define OFF_XL (XROWS * XSTR * 2)     // 56160
#define OFF_B (2 * XROWS * XSTR * 2)  // 112320
#define BPLANE (64 * XSTR * 2)        // 9216 bytes per plane
#define CONV_SMEM (OFF_B + 4 * BPLANE)  // 149184

__global__ void __launch_bounds__(256, 1)
conv_kernel(const float* __restrict__ x, float* __restrict__ out) {
    extern __shared__ char smem[];
    __nv_bfloat16* XH = (__nv_bfloat16*)(smem + OFF_XH);
    __nv_bfloat16* XL = (__nv_bfloat16*)(smem + OFF_XL);
    const int tid = threadIdx.x;
    const int lane = tid & 31, wid = tid >> 5;
    const int wm = wid & 3, wnw = wid >> 2;  // 4 x 2 warp grid
    const int b = blockIdx.y;
    const int y = blockIdx.x >> 1;
    const int x0 = (blockIdx.x & 1) * 128;

    // ---- stage X (hi/lo split planes) ----
    const float* xb = x + (size_t)b * NC * (NH * NW);
    for (int i = tid; i < NC * 3 * 130; i += 256) {
        int col = i % 130;
        int t = i / 130;
        int r = t % 3;
        int c = t / 3;
        int gy = y - 1 + r, gx = x0 - 1 + col;
        float v = 0.f;
        if ((unsigned)gy < 256u && (unsigned)gx < 256u)
            v = xb[c * (NH * NW) + gy * NW + gx];
        __nv_bfloat16 hi = __float2bfloat16(v);
        __nv_bfloat16 lo = __float2bfloat16(v - __bfloat162float(hi));
        int row = r * 130 + col;
        XH[row * XSTR + c] = hi;
        XL[row * XSTR + c] = lo;
    }

    // ---- prefetch B for tap 0 ----
    const unsigned* wsrc = g_aggws + (size_t)b * 9 * (NC * NO);
    const int bo = tid & 63;          // output channel
    const int bcg = (tid >> 6) * 16;  // channel-group base
    unsigned wreg[16];
#pragma unroll
    for (int u = 0; u < 16; u++) wreg[u] = wsrc[(bcg + u) * NO + bo];

    float acc[2][4][4];
#pragma unroll
    for (int mt = 0; mt < 2; mt++)
#pragma unroll
        for (int tn = 0; tn < 4; tn++)
#pragma unroll
            for (int r = 0; r < 4; r++) acc[mt][tn][r] = 0.f;

    const unsigned sXH = smem_u32(XH);
    const unsigned sXL = smem_u32(XL);

#pragma unroll 1
    for (int tap = 0; tap < 9; tap++) {
        const int buf = tap & 1;
        __nv_bfloat16* BH = (__nv_bfloat16*)(smem + OFF_B + buf * 2 * BPLANE);
        __nv_bfloat16* BL = BH + 64 * XSTR;
#pragma unroll
        for (int u = 0; u < 16; u++) {
            int c = bcg + u;
            BH[bo * XSTR + c] = __ushort_as_bfloat16((unsigned short)(wreg[u] & 0xFFFF));
            BL[bo * XSTR + c] = __ushort_as_bfloat16((unsigned short)(wreg[u] >> 16));
        }
        __syncthreads();
        if (tap < 8) {
            const unsigned* wnx = wsrc + (tap + 1) * (NC * NO);
#pragma unroll
            for (int u = 0; u < 16; u++) wreg[u] = wnx[(bcg + u) * NO + bo];
        }

        const int ky = tap / 3, kx = tap % 3;
        // A row for pixel m: ky*130 + m + kx
        const int arow = ky * 130 + kx + wm * 32 + (lane & 15);
        const int acolb = ((lane & 16) ? 8 : 0) * 2;  // byte offset of col half

#pragma unroll
        for (int term = 0; term < 3; term++) {
            const unsigned aplane = (term == 1) ? sXL : sXH;
            const __nv_bfloat16* Bp = (term == 2) ? BL : BH;
#pragma unroll
            for (int kc = 0; kc < 4; kc++) {
                unsigned a0, a1, a2, a3, e0, e1, e2, e3;
                unsigned ad = aplane + (unsigned)(arow * (XSTR * 2) + kc * 32 + acolb);
                ldmatrix_x4(a0, a1, a2, a3, ad);
                ldmatrix_x4(e0, e1, e2, e3, ad + 16 * (XSTR * 2));
#pragma unroll
                for (int tn = 0; tn < 4; tn++) {
                    int n = wnw * 32 + tn * 8 + (lane >> 2);
                    int c = kc * 16 + (lane & 3) * 2;
                    unsigned b0 = *(const unsigned*)(Bp + n * XSTR + c);
                    unsigned b1 = *(const unsigned*)(Bp + n * XSTR + c + 8);
                    mma16816(acc[0][tn], a0, a1, a2, a3, b0, b1);
                    mma16816(acc[1][tn], e0, e1, e2, e3, b0, b1);
                }
            }
        }
        __syncthreads();
    }

    // ---- epilogue: bias + store ----
#pragma unroll
    for (int mt = 0; mt < 2; mt++) {
        int m0 = x0 + wm * 32 + mt * 16 + (lane >> 2);
#pragma unroll
        for (int tn = 0; tn < 4; tn++) {
            int n0 = wnw * 32 + tn * 8 + (lane & 3) * 2;
            float bv0 = g_aggb[b * NO + n0];
            float bv1 = g_aggb[b * NO + n0 + 1];
            size_t p0 = ((size_t)(b * NO + n0) * NH + y) * NW;
            size_t p1 = ((size_t)(b * NO + n0 + 1) * NH + y) * NW;
            out[p0 + m0] = acc[mt][tn][0] + bv0;
            out[p1 + m0] = acc[mt][tn][1] + bv1;
            out[p0 + m0 + 8] = acc[mt][tn][2] + bv0;
            out[p1 + m0 + 8] = acc[mt][tn][3] + bv1;
        }
    }
}

// ---------------------------------------------------------------------------
extern "C" void kernel_launch(void* const* d_in, const int* in_sizes, int n_in,
                              void* d_out, int out_size) {
    const float* x      = (const float*)d_in[0];
    const float* fc1_w  = (const float*)d_in[1];
    const float* fc2_w  = (const float*)d_in[2];
    const float* fc2_b  = (const float*)d_in[3];
    const float* weight = (const float*)d_in[4];
    const float* bias_k = (const float*)d_in[5];
    float* out = (float*)d_out;

    cudaFuncSetAttribute(conv_kernel, cudaFuncAttributeMaxDynamicSharedMemorySize,
                         CONV_SMEM);

    pool_kernel<<<NB * NC, 256>>>(x);
    att_kernel<<<1, 288>>>(fc1_w, fc2_w, fc2_b);
    agg_kernel<<<(NB * 9 * NC * NO + 255) / 256, 256>>>(weight, bias_k);
    conv_kernel<<<dim3(NH * 2, NB), 256, CONV_SMEM>>>(x, out);
}

// round 7
// speedup vs baseline: 2.3642x; 1.9824x over previous
#include <cuda_runtime.h>
#include <cuda_bf16.h>
#include <cstdint>

#define NB 16
#define NC 64
#define NH 256
#define NW 256
#define NK 4
#define NO 64
#define HID 17
#define TEMP 34.0f
#define SLOPE 0.2f

// Scratch
__device__ float g_pooled[NB * NC];
__device__ float g_att[NB * NK];
__device__ __align__(16) __nv_bfloat16 g_awhi[NB * 9 * NO * NC];  // [b][tap][o][c]
__device__ __align__(16) __nv_bfloat16 g_awlo[NB * 9 * NO * NC];
__device__ float g_aggb[NB * NO];

__device__ __forceinline__ unsigned smem_u32(const void* p) {
    unsigned a;
    asm("{ .reg .u64 t; cvta.to.shared.u64 t, %1; cvt.u32.u64 %0, t; }" : "=r"(a) : "l"(p));
    return a;
}

__device__ __forceinline__ void ldmatrix_x4(unsigned& r0, unsigned& r1, unsigned& r2,
                                            unsigned& r3, unsigned addr) {
    asm volatile("ldmatrix.sync.aligned.m8n8.x4.shared.b16 {%0,%1,%2,%3}, [%4];"
                 : "=r"(r0), "=r"(r1), "=r"(r2), "=r"(r3) : "r"(addr));
}

__device__ __forceinline__ void mma16816(float* d, unsigned a0, unsigned a1, unsigned a2,
                                         unsigned a3, unsigned b0, unsigned b1) {
    asm volatile(
        "mma.sync.aligned.m16n8k16.row.col.f32.bf16.bf16.f32 "
        "{%0,%1,%2,%3}, {%4,%5,%6,%7}, {%8,%9}, {%0,%1,%2,%3};"
        : "+f"(d[0]), "+f"(d[1]), "+f"(d[2]), "+f"(d[3])
        : "r"(a0), "r"(a1), "r"(a2), "r"(a3), "r"(b0), "r"(b1));
}

__device__ __forceinline__ void cp16(unsigned dst, const void* src) {
    asm volatile("cp.async.ca.shared.global [%0], [%1], 16;" :: "r"(dst), "l"(src));
}

// ---------------------------------------------------------------------------
// Kernel 1: global average pool
// ---------------------------------------------------------------------------
__global__ void pool_kernel(const float* __restrict__ x) {
    int bc = blockIdx.x;
    const float4* p = reinterpret_cast<const float4*>(x) + (size_t)bc * (NH * NW / 4);
    float s = 0.f;
    for (int i = threadIdx.x; i < NH * NW / 4; i += 256) {
        float4 v = p[i];
        s += (v.x + v.y) + (v.z + v.w);
    }
#pragma unroll
    for (int off = 16; off; off >>= 1) s += __shfl_down_sync(0xFFFFFFFFu, s, off);
    __shared__ float ws[8];
    if ((threadIdx.x & 31) == 0) ws[threadIdx.x >> 5] = s;
    __syncthreads();
    if (threadIdx.x == 0) {
        float tot = 0.f;
#pragma unroll
        for (int w = 0; w < 8; w++) tot += ws[w];
        g_pooled[bc] = tot * (1.0f / (NH * NW));
    }
}

// ---------------------------------------------------------------------------
// Kernel 2: attention MLP + softmax
// ---------------------------------------------------------------------------
__global__ void att_kernel(const float* __restrict__ fc1,
                           const float* __restrict__ fc2,
                           const float* __restrict__ fc2b) {
    __shared__ float sp[NB * NC];
    __shared__ float sf1[HID * NC];
    __shared__ float sh[NB][HID];
    int t = threadIdx.x;
    for (int i = t; i < NB * NC; i += blockDim.x) sp[i] = g_pooled[i];
    for (int i = t; i < HID * NC; i += blockDim.x) sf1[i] = fc1[i];
    __syncthreads();
    if (t < NB * HID) {
        int b = t / HID, j = t % HID;
        float s = 0.f;
#pragma unroll
        for (int c = 0; c < NC; c++) s += sp[b * NC + c] * sf1[j * NC + c];
        sh[b][j] = s >= 0.f ? s : SLOPE * s;
    }
    __syncthreads();
    if (t < NB) {
        int b = t;
        float lg[NK];
        float m = -1e30f;
#pragma unroll
        for (int k = 0; k < NK; k++) {
            float s = fc2b[k];
#pragma unroll
            for (int j = 0; j < HID; j++) s += sh[b][j] * fc2[k * HID + j];
            lg[k] = s / TEMP;
            m = fmaxf(m, lg[k]);
        }
        float den = 0.f, e[NK];
#pragma unroll
        for (int k = 0; k < NK; k++) { e[k] = expf(lg[k] - m); den += e[k]; }
        float inv = 1.0f / den;
#pragma unroll
        for (int k = 0; k < NK; k++) g_att[b * NK + k] = e[k] * inv;
    }
}

// ---------------------------------------------------------------------------
// Kernel 3: aggregate weights -> split bf16 planes, layout [b][tap][o][c]
// ---------------------------------------------------------------------------
__global__ void agg_kernel(const float* __restrict__ weight,  // [K][O][I][3][3]
                           const float* __restrict__ bias_k) {
    int idx = blockIdx.x * 256 + threadIdx.x;
    const int TOT = NB * 9 * NC * NO;  // 589824
    if (idx < TOT) {
        int c = idx & 63;
        int t1 = idx >> 6;
        int o = t1 & 63;
        int t2 = t1 >> 6;
        int tap = t2 % 9;
        int b = t2 / 9;
        const int KS = NO * NC * 9;
        int wb = (o * NC + c) * 9 + tap;
        float s = g_att[b * NK + 0] * weight[wb] +
                  g_att[b * NK + 1] * weight[wb + KS] +
                  g_att[b * NK + 2] * weight[wb + 2 * KS] +
                  g_att[b * NK + 3] * weight[wb + 3 * KS];
        __nv_bfloat16 hi = __float2bfloat16(s);
        float r = s - __bfloat162float(hi);
        g_awhi[idx] = hi;
        g_awlo[idx] = __float2bfloat16(r);
    }
    if (idx < NB * NO) {
        int b = idx >> 6, o = idx & 63;
        float s = 0.f;
#pragma unroll
        for (int k = 0; k < NK; k++) s += g_att[b * NK + k] * bias_k[k * NO + o];
        g_aggb[idx] = s;
    }
}

// ---------------------------------------------------------------------------
// Kernel 4: mma.sync bf16 implicit-GEMM conv. 512 threads, 16 warps (4m x 4n).
// CTA = (b, y, half): M=128 px x N=64 out, K = 9 taps x 64 ch x 3 split terms.
// X planes [3*130 rows][64 ch] bf16, row stride 72 (144 B, conflict-free).
// B double-buffered via cp.async; A ldmatrix software-pipelined.
// ---------------------------------------------------------------------------
#define XSTR 72
#define XROWS (3 * 130)
#define OFF_XH 0
#define OFF_XL (XROWS * XSTR * 2)       // 56160
#define OFF_B (2 * XROWS * XSTR * 2)    // 112320
#define BPLANE (64 * XSTR * 2)          // 9216 B
#define CONV_SMEM (OFF_B + 4 * BPLANE)  // 149184

__global__ void __launch_bounds__(512, 1)
conv_kernel(const float* __restrict__ x, float* __restrict__ out) {
    extern __shared__ char smem[];
    __nv_bfloat16* XH = (__nv_bfloat16*)(smem + OFF_XH);
    __nv_bfloat16* XL = (__nv_bfloat16*)(smem + OFF_XL);
    const unsigned sb = smem_u32(smem);
    const int tid = threadIdx.x;
    const int lane = tid & 31, wid = tid >> 5;
    const int wm = wid & 3, wn = wid >> 2;  // 4 x 4 warp grid
    const int b = blockIdx.y;
    const int y = blockIdx.x >> 1;
    const int x0 = (blockIdx.x & 1) * 128;

    // ---- B staging helper (cp.async, 2 chunks of 16B per thread per tap) ----
    const __nv_bfloat16* awh = g_awhi + (size_t)b * 9 * (NO * NC);
    const __nv_bfloat16* awl = g_awlo + (size_t)b * 9 * (NO * NC);
#define STAGE_B(TAP, BUF)                                                        \
    {                                                                            \
        _Pragma("unroll")                                                        \
        for (int j = 0; j < 2; j++) {                                            \
            int q = tid + j * 512;                                               \
            int plane = q >> 9, rem = q & 511;                                   \
            int o = rem >> 3, ck = rem & 7;                                      \
            const __nv_bfloat16* srcb = plane ? awl : awh;                       \
            const void* src = srcb + ((TAP) * NO + o) * NC + ck * 8;             \
            unsigned dst = sb + OFF_B + (BUF) * 2 * BPLANE + plane * BPLANE +    \
                           o * (XSTR * 2) + ck * 16;                             \
            cp16(dst, src);                                                      \
        }                                                                        \
        asm volatile("cp.async.commit_group;");                                  \
    }

    STAGE_B(0, 0);  // overlap with X staging below

    // ---- stage X (hi/lo split planes) ----
    const float* xb = x + (size_t)b * NC * (NH * NW);
    for (int i = tid; i < NC * 3 * 130; i += 512) {
        int col = i % 130;
        int t = i / 130;
        int r = t % 3;
        int c = t / 3;
        int gy = y - 1 + r, gx = x0 - 1 + col;
        float v = 0.f;
        if ((unsigned)gy < 256u && (unsigned)gx < 256u)
            v = xb[c * (NH * NW) + gy * NW + gx];
        __nv_bfloat16 hi = __float2bfloat16(v);
        __nv_bfloat16 lo = __float2bfloat16(v - __bfloat162float(hi));
        int row = r * 130 + col;
        XH[row * XSTR + c] = hi;
        XL[row * XSTR + c] = lo;
    }

    float acc[2][2][4];
#pragma unroll
    for (int mt = 0; mt < 2; mt++)
#pragma unroll
        for (int tn = 0; tn < 2; tn++)
#pragma unroll
            for (int r = 0; r < 4; r++) acc[mt][tn][r] = 0.f;

    const unsigned sXH = sb + OFF_XH;
    const unsigned sXL = sb + OFF_XL;
    const int acolb = ((lane & 16) ? 8 : 0) * 2;

#pragma unroll 1
    for (int tap = 0; tap < 9; tap++) {
        const int buf = tap & 1;
        if (tap < 8) {
            STAGE_B(tap + 1, buf ^ 1);
            asm volatile("cp.async.wait_group 1;");
        } else {
            asm volatile("cp.async.wait_group 0;");
        }
        __syncthreads();  // B(tap) visible to all; also fences buf reuse & X (tap 0)

        const __nv_bfloat16* BH = (const __nv_bfloat16*)(smem + OFF_B + buf * 2 * BPLANE);
        const __nv_bfloat16* BL = BH + 64 * XSTR;

        const int ky = tap / 3, kx = tap % 3;
        const int arow = ky * 130 + kx + wm * 32 + (lane & 15);
        const unsigned abase = (unsigned)(arow * (XSTR * 2) + acolb);

        // A pipeline over 12 (term,kc) steps
        unsigned ac[8], an[8];
        {
            unsigned ad = sXH + abase;  // it=0: term 0, kc 0
            ldmatrix_x4(ac[0], ac[1], ac[2], ac[3], ad);
            ldmatrix_x4(ac[4], ac[5], ac[6], ac[7], ad + 16 * (XSTR * 2));
        }
#pragma unroll
        for (int it = 0; it < 12; it++) {
            const int term = it >> 2, kc = it & 3;
            if (it < 11) {
                const int t2 = (it + 1) >> 2, k2 = (it + 1) & 3;
                unsigned ad = ((t2 == 1) ? sXL : sXH) + abase + (unsigned)(k2 * 32);
                ldmatrix_x4(an[0], an[1], an[2], an[3], ad);
                ldmatrix_x4(an[4], an[5], an[6], an[7], ad + 16 * (XSTR * 2));
            }
            const __nv_bfloat16* Bp = (term == 2) ? BL : BH;
#pragma unroll
            for (int tn = 0; tn < 2; tn++) {
                int n = wn * 16 + tn * 8 + (lane >> 2);
                int c = kc * 16 + (lane & 3) * 2;
                unsigned b0 = *(const unsigned*)(Bp + n * XSTR + c);
                unsigned b1 = *(const unsigned*)(Bp + n * XSTR + c + 8);
                mma16816(acc[0][tn], ac[0], ac[1], ac[2], ac[3], b0, b1);
                mma16816(acc[1][tn], ac[4], ac[5], ac[6], ac[7], b0, b1);
            }
#pragma unroll
            for (int r = 0; r < 8; r++) ac[r] = an[r];
        }
    }

    // ---- epilogue: bias + store ----
#pragma unroll
    for (int mt = 0; mt < 2; mt++) {
        int m0 = x0 + wm * 32 + mt * 16 + (lane >> 2);
#pragma unroll
        for (int tn = 0; tn < 2; tn++) {
            int n0 = wn * 16 + tn * 8 + (lane & 3) * 2;
            float bv0 = g_aggb[b * NO + n0];
            float bv1 = g_aggb[b * NO + n0 + 1];
            size_t p0 = ((size_t)(b * NO + n0) * NH + y) * NW;
            size_t p1 = ((size_t)(b * NO + n0 + 1) * NH + y) * NW;
            out[p0 + m0] = acc[mt][tn][0] + bv0;
            out[p1 + m0] = acc[mt][tn][1] + bv1;
            out[p0 + m0 + 8] = acc[mt][tn][2] + bv0;
            out[p1 + m0 + 8] = acc[mt][tn][3] + bv1;
        }
    }
#undef STAGE_B
}

// ---------------------------------------------------------------------------
extern "C" void kernel_launch(void* const* d_in, const int* in_sizes, int n_in,
                              void* d_out, int out_size) {
    const float* x      = (const float*)d_in[0];
    const float* fc1_w  = (const float*)d_in[1];
    const float* fc2_w  = (const float*)d_in[2];
    const float* fc2_b  = (const float*)d_in[3];
    const float* weight = (const float*)d_in[4];
    const float* bias_k = (const float*)d_in[5];
    float* out = (float*)d_out;

    cudaFuncSetAttribute(conv_kernel, cudaFuncAttributeMaxDynamicSharedMemorySize,
                         CONV_SMEM);

    pool_kernel<<<NB * NC, 256>>>(x);
    att_kernel<<<1, 288>>>(fc1_w, fc2_w, fc2_b);
    agg_kernel<<<(NB * 9 * NC * NO + 255) / 256, 256>>>(weight, bias_k);
    conv_kernel<<<dim3(NH * 2, NB), 512, CONV_SMEM>>>(x, out);
}

// round 8
// speedup vs baseline: 2.5862x; 1.0939x over previous
#include <cuda_runtime.h>
#include <cuda_bf16.h>
#include <cstdint>

#define NB 16
#define NC 64
#define NH 256
#define NW 256
#define NK 4
#define NO 64
#define HID 17
#define TEMP 34.0f
#define SLOPE 0.2f

// Scratch (device globals; allocation-free rule)
__device__ float g_pooled[NB * NC];
__device__ float g_att[NB * NK];
__device__ __align__(16) __nv_bfloat16 g_awhi[NB * 9 * NO * NC];  // [b][tap][o][c]
__device__ __align__(16) __nv_bfloat16 g_awlo[NB * 9 * NO * NC];
__device__ float g_aggb[NB * NO];
// Pre-split, transposed input: [b][h][w][c], hi/lo planes (128 MB each)
__device__ __align__(16) __nv_bfloat16 g_xhi[(size_t)NB * NH * NW * NC];
__device__ __align__(16) __nv_bfloat16 g_xlo[(size_t)NB * NH * NW * NC];

__device__ __forceinline__ unsigned smem_u32(const void* p) {
    unsigned a;
    asm("{ .reg .u64 t; cvta.to.shared.u64 t, %1; cvt.u32.u64 %0, t; }" : "=r"(a) : "l"(p));
    return a;
}
__device__ __forceinline__ void ldmatrix_x4(unsigned& r0, unsigned& r1, unsigned& r2,
                                            unsigned& r3, unsigned addr) {
    asm volatile("ldmatrix.sync.aligned.m8n8.x4.shared.b16 {%0,%1,%2,%3}, [%4];"
                 : "=r"(r0), "=r"(r1), "=r"(r2), "=r"(r3) : "r"(addr));
}
__device__ __forceinline__ void mma16816(float* d, unsigned a0, unsigned a1, unsigned a2,
                                         unsigned a3, unsigned b0, unsigned b1) {
    asm volatile(
        "mma.sync.aligned.m16n8k16.row.col.f32.bf16.bf16.f32 "
        "{%0,%1,%2,%3}, {%4,%5,%6,%7}, {%8,%9}, {%0,%1,%2,%3};"
        : "+f"(d[0]), "+f"(d[1]), "+f"(d[2]), "+f"(d[3])
        : "r"(a0), "r"(a1), "r"(a2), "r"(a3), "r"(b0), "r"(b1));
}
__device__ __forceinline__ void cp16(unsigned dst, const void* src) {
    asm volatile("cp.async.ca.shared.global [%0], [%1], 16;" :: "r"(dst), "l"(src));
}
__device__ __forceinline__ void cp16z(unsigned dst, const void* src, int sz) {
    asm volatile("cp.async.ca.shared.global [%0], [%1], 16, %2;"
                 :: "r"(dst), "l"(src), "r"(sz));
}

// ---------------------------------------------------------------------------
// Kernel 0: split x into bf16 hi/lo planes, transposed to [b][h][w][c].
// One block per (b,h); smem transpose; coalesced LDG and STG.
// ---------------------------------------------------------------------------
#define SPL_STR 66  // bf16 stride (33 banks -> conflict-free both phases)
#define SPL_SMEM (2 * NW * SPL_STR * 2)  // 67584 B

__global__ void __launch_bounds__(256, 1)
split_kernel(const float* __restrict__ x) {
    extern __shared__ __nv_bfloat16 sp[];
    __nv_bfloat16* SH = sp;
    __nv_bfloat16* SL = sp + NW * SPL_STR;
    const int bh = blockIdx.x;
    const int b = bh >> 8, h = bh & 255;
    const int tid = threadIdx.x;  // = w
    const float* xb = x + ((size_t)b * NC * NH + h) * NW;
#pragma unroll 4
    for (int c = 0; c < NC; c++) {
        float v = xb[(size_t)c * (NH * NW) + tid];
        __nv_bfloat16 hi = __float2bfloat16(v);
        __nv_bfloat16 lo = __float2bfloat16(v - __bfloat162float(hi));
        SH[tid * SPL_STR + c] = hi;
        SL[tid * SPL_STR + c] = lo;
    }
    __syncthreads();
    unsigned* oh = (unsigned*)(g_xhi + (size_t)bh * NW * NC);
    unsigned* ol = (unsigned*)(g_xlo + (size_t)bh * NW * NC);
    const unsigned* sh32 = (const unsigned*)SH;
    const unsigned* sl32 = (const unsigned*)SL;
#pragma unroll
    for (int i = tid; i < NW * 32; i += 256) {
        int w = i >> 5, c2 = i & 31;
        oh[w * 32 + c2] = sh32[w * 33 + c2];  // SPL_STR/2 = 33 u32 per row
        ol[w * 32 + c2] = sl32[w * 33 + c2];
    }
}

// ---------------------------------------------------------------------------
// Kernel 1: global average pool
// ---------------------------------------------------------------------------
__global__ void pool_kernel(const float* __restrict__ x) {
    int bc = blockIdx.x;
    const float4* p = reinterpret_cast<const float4*>(x) + (size_t)bc * (NH * NW / 4);
    float s = 0.f;
    for (int i = threadIdx.x; i < NH * NW / 4; i += 256) {
        float4 v = p[i];
        s += (v.x + v.y) + (v.z + v.w);
    }
#pragma unroll
    for (int off = 16; off; off >>= 1) s += __shfl_down_sync(0xFFFFFFFFu, s, off);
    __shared__ float ws[8];
    if ((threadIdx.x & 31) == 0) ws[threadIdx.x >> 5] = s;
    __syncthreads();
    if (threadIdx.x == 0) {
        float tot = 0.f;
#pragma unroll
        for (int w = 0; w < 8; w++) tot += ws[w];
        g_pooled[bc] = tot * (1.0f / (NH * NW));
    }
}

// ---------------------------------------------------------------------------
// Kernel 2: attention MLP + softmax
// ---------------------------------------------------------------------------
__global__ void att_kernel(const float* __restrict__ fc1,
                           const float* __restrict__ fc2,
                           const float* __restrict__ fc2b) {
    __shared__ float sp[NB * NC];
    __shared__ float sf1[HID * NC];
    __shared__ float sh[NB][HID];
    int t = threadIdx.x;
    for (int i = t; i < NB * NC; i += blockDim.x) sp[i] = g_pooled[i];
    for (int i = t; i < HID * NC; i += blockDim.x) sf1[i] = fc1[i];
    __syncthreads();
    if (t < NB * HID) {
        int b = t / HID, j = t % HID;
        float s = 0.f;
#pragma unroll
        for (int c = 0; c < NC; c++) s += sp[b * NC + c] * sf1[j * NC + c];
        sh[b][j] = s >= 0.f ? s : SLOPE * s;
    }
    __syncthreads();
    if (t < NB) {
        int b = t;
        float lg[NK];
        float m = -1e30f;
#pragma unroll
        for (int k = 0; k < NK; k++) {
            float s = fc2b[k];
#pragma unroll
            for (int j = 0; j < HID; j++) s += sh[b][j] * fc2[k * HID + j];
            lg[k] = s / TEMP;
            m = fmaxf(m, lg[k]);
        }
        float den = 0.f, e[NK];
#pragma unroll
        for (int k = 0; k < NK; k++) { e[k] = expf(lg[k] - m); den += e[k]; }
        float inv = 1.0f / den;
#pragma unroll
        for (int k = 0; k < NK; k++) g_att[b * NK + k] = e[k] * inv;
    }
}

// ---------------------------------------------------------------------------
// Kernel 3: aggregate weights -> split bf16 planes, layout [b][tap][o][c]
// ---------------------------------------------------------------------------
__global__ void agg_kernel(const float* __restrict__ weight,
                           const float* __restrict__ bias_k) {
    int idx = blockIdx.x * 256 + threadIdx.x;
    const int TOT = NB * 9 * NC * NO;
    if (idx < TOT) {
        int c = idx & 63;
        int t1 = idx >> 6;
        int o = t1 & 63;
        int t2 = t1 >> 6;
        int tap = t2 % 9;
        int b = t2 / 9;
        const int KS = NO * NC * 9;
        int wb = (o * NC + c) * 9 + tap;
        float s = g_att[b * NK + 0] * weight[wb] +
                  g_att[b * NK + 1] * weight[wb + KS] +
                  g_att[b * NK + 2] * weight[wb + 2 * KS] +
                  g_att[b * NK + 3] * weight[wb + 3 * KS];
        __nv_bfloat16 hi = __float2bfloat16(s);
        g_awhi[idx] = hi;
        g_awlo[idx] = __float2bfloat16(s - __bfloat162float(hi));
    }
    if (idx < NB * NO) {
        int b = idx >> 6, o = idx & 63;
        float s = 0.f;
#pragma unroll
        for (int k = 0; k < NK; k++) s += g_att[b * NK + k] * bias_k[k * NO + o];
        g_aggb[idx] = s;
    }
}

// ---------------------------------------------------------------------------
// Kernel 4: mma.sync bf16 implicit-GEMM conv. 512 thr, 16 warps (4m x 4n).
// X staged via pure cp.async from pre-split planes; B cp.async double-buffered.
// kc-outer loop reuses A hi/lo fragments across the 3 split terms.
// ---------------------------------------------------------------------------
#define XSTR 72                          // bf16 per row (144 B, conflict-free)
#define XROWS (3 * 130)                  // 390
#define OFF_XH 0
#define OFF_XL (XROWS * XSTR * 2)        // 56160
#define OFF_B (2 * XROWS * XSTR * 2)     // 112320
#define BPLANE (64 * XSTR * 2)           // 9216 B
#define CONV_SMEM (OFF_B + 4 * BPLANE)   // 149184

__global__ void __launch_bounds__(512, 1)
conv_kernel(float* __restrict__ out) {
    extern __shared__ char smem[];
    const unsigned sb = smem_u32(smem);
    const int tid = threadIdx.x;
    const int lane = tid & 31, wid = tid >> 5;
    const int wm = wid & 3, wn = wid >> 2;
    const int b = blockIdx.y;
    const int y = blockIdx.x >> 1;
    const int x0 = (blockIdx.x & 1) * 128;

    // ---- stage X via cp.async (hi/lo planes, halo zero-filled) ----
    {
        const size_t bbase = (size_t)b * NH * NW * NC;
        for (int i = tid; i < XROWS * 16; i += 512) {
            int row = i >> 4;
            int rem = i & 15;
            int plane = rem >> 3, ck = rem & 7;
            int r = row / 130, col = row - r * 130;
            int gy = y - 1 + r, gx = x0 - 1 + col;
            bool ok = ((unsigned)gy < 256u) && ((unsigned)gx < 256u);
            const __nv_bfloat16* base = plane ? g_xlo : g_xhi;
            const void* src = base + bbase + (((size_t)gy * NW + (ok ? gx : 0)) * NC) + ck * 8;
            unsigned dst = sb + (plane ? OFF_XL : OFF_XH) + row * (XSTR * 2) + ck * 16;
            cp16z(dst, src, ok ? 16 : 0);
        }
        asm volatile("cp.async.commit_group;");
    }

    // ---- B staging (cp.async) ----
    const __nv_bfloat16* awh = g_awhi + (size_t)b * 9 * (NO * NC);
    const __nv_bfloat16* awl = g_awlo + (size_t)b * 9 * (NO * NC);
#define STAGE_B(TAP, BUF)                                                        \
    {                                                                            \
        _Pragma("unroll")                                                        \
        for (int j = 0; j < 2; j++) {                                            \
            int q = tid + j * 512;                                               \
            int plane = q >> 9, rem = q & 511;                                   \
            int o = rem >> 3, ck = rem & 7;                                      \
            const __nv_bfloat16* srcb = plane ? awl : awh;                       \
            const void* src = srcb + ((TAP) * NO + o) * NC + ck * 8;             \
            unsigned dst = sb + OFF_B + (BUF) * 2 * BPLANE + plane * BPLANE +    \
                           o * (XSTR * 2) + ck * 16;                             \
            cp16(dst, src);                                                      \
        }                                                                        \
        asm volatile("cp.async.commit_group;");                                  \
    }

    STAGE_B(0, 0);

    float acc[2][2][4];
#pragma unroll
    for (int mt = 0; mt < 2; mt++)
#pragma unroll
        for (int tn = 0; tn < 2; tn++)
#pragma unroll
            for (int r = 0; r < 4; r++) acc[mt][tn][r] = 0.f;

    const unsigned sXH = sb + OFF_XH;
    const unsigned sXL = sb + OFF_XL;
    const int acolb = (lane & 16) ? 16 : 0;

#pragma unroll 1
    for (int tap = 0; tap < 9; tap++) {
        const int buf = tap & 1;
        if (tap < 8) {
            STAGE_B(tap + 1, buf ^ 1);
            asm volatile("cp.async.wait_group 1;");
        } else {
            asm volatile("cp.async.wait_group 0;");
        }
        __syncthreads();

        const __nv_bfloat16* BH = (const __nv_bfloat16*)(smem + OFF_B + buf * 2 * BPLANE);
        const __nv_bfloat16* BL = BH + 64 * XSTR;

        const int ky = tap / 3, kx = tap % 3;
        const int arow = ky * 130 + kx + wm * 32 + (lane & 15);
        const unsigned abase = (unsigned)(arow * (XSTR * 2) + acolb);

        unsigned hc[8], lc[8], hn[8], ln[8];
        {
            unsigned adh = sXH + abase, adl = sXL + abase;
            ldmatrix_x4(hc[0], hc[1], hc[2], hc[3], adh);
            ldmatrix_x4(hc[4], hc[5], hc[6], hc[7], adh + 16 * (XSTR * 2));
            ldmatrix_x4(lc[0], lc[1], lc[2], lc[3], adl);
            ldmatrix_x4(lc[4], lc[5], lc[6], lc[7], adl + 16 * (XSTR * 2));
        }
#pragma unroll
        for (int kc = 0; kc < 4; kc++) {
            if (kc < 3) {
                unsigned adh = sXH + abase + (unsigned)((kc + 1) * 32);
                unsigned adl = sXL + abase + (unsigned)((kc + 1) * 32);
                ldmatrix_x4(hn[0], hn[1], hn[2], hn[3], adh);
                ldmatrix_x4(hn[4], hn[5], hn[6], hn[7], adh + 16 * (XSTR * 2));
                ldmatrix_x4(ln[0], ln[1], ln[2], ln[3], adl);
                ldmatrix_x4(ln[4], ln[5], ln[6], ln[7], adl + 16 * (XSTR * 2));
            }
#pragma unroll
            for (int tn = 0; tn < 2; tn++) {
                int n = wn * 16 + tn * 8 + (lane >> 2);
                int c = kc * 16 + (lane & 3) * 2;
                unsigned bh0 = *(const unsigned*)(BH + n * XSTR + c);
                unsigned bh1 = *(const unsigned*)(BH + n * XSTR + c + 8);
                unsigned bl0 = *(const unsigned*)(BL + n * XSTR + c);
                unsigned bl1 = *(const unsigned*)(BL + n * XSTR + c + 8);
                // term 0: Ahi x Bhi
                mma16816(acc[0][tn], hc[0], hc[1], hc[2], hc[3], bh0, bh1);
                mma16816(acc[1][tn], hc[4], hc[5], hc[6], hc[7], bh0, bh1);
                // term 1: Alo x Bhi
                mma16816(acc[0][tn], lc[0], lc[1], lc[2], lc[3], bh0, bh1);
                mma16816(acc[1][tn], lc[4], lc[5], lc[6], lc[7], bh0, bh1);
                // term 2: Ahi x Blo
                mma16816(acc[0][tn], hc[0], hc[1], hc[2], hc[3], bl0, bl1);
                mma16816(acc[1][tn], hc[4], hc[5], hc[6], hc[7], bl0, bl1);
            }
#pragma unroll
            for (int r = 0; r < 8; r++) { hc[r] = hn[r]; lc[r] = ln[r]; }
        }
    }

    // ---- epilogue: bias + store ----
#pragma unroll
    for (int mt = 0; mt < 2; mt++) {
        int m0 = x0 + wm * 32 + mt * 16 + (lane >> 2);
#pragma unroll
        for (int tn = 0; tn < 2; tn++) {
            int n0 = wn * 16 + tn * 8 + (lane & 3) * 2;
            float bv0 = g_aggb[b * NO + n0];
            float bv1 = g_aggb[b * NO + n0 + 1];
            size_t p0 = ((size_t)(b * NO + n0) * NH + y) * NW;
            size_t p1 = ((size_t)(b * NO + n0 + 1) * NH + y) * NW;
            out[p0 + m0] = acc[mt][tn][0] + bv0;
            out[p1 + m0] = acc[mt][tn][1] + bv1;
            out[p0 + m0 + 8] = acc[mt][tn][2] + bv0;
            out[p1 + m0 + 8] = acc[mt][tn][3] + bv1;
        }
    }
#undef STAGE_B
}

// ---------------------------------------------------------------------------
extern "C" void kernel_launch(void* const* d_in, const int* in_sizes, int n_in,
                              void* d_out, int out_size) {
    const float* x      = (const float*)d_in[0];
    const float* fc1_w  = (const float*)d_in[1];
    const float* fc2_w  = (const float*)d_in[2];
    const float* fc2_b  = (const float*)d_in[3];
    const float* weight = (const float*)d_in[4];
    const float* bias_k = (const float*)d_in[5];
    float* out = (float*)d_out;

    cudaFuncSetAttribute(split_kernel, cudaFuncAttributeMaxDynamicSharedMemorySize,
                         SPL_SMEM);
    cudaFuncSetAttribute(conv_kernel, cudaFuncAttributeMaxDynamicSharedMemorySize,
                         CONV_SMEM);

    split_kernel<<<NB * NH, 256, SPL_SMEM>>>(x);
    pool_kernel<<<NB * NC, 256>>>(x);
    att_kernel<<<1, 288>>>(fc1_w, fc2_w, fc2_b);
    agg_kernel<<<(NB * 9 * NC * NO + 255) / 256, 256>>>(weight, bias_k);
    conv_kernel<<<dim3(NH * 2, NB), 512, CONV_SMEM>>>(out);
}